// round 3
// baseline (speedup 1.0000x reference)
#include <cuda_runtime.h>
#include <math.h>

// Problem constants (fixed by the dataset)
#define D        512      // class_dim
#define REL      53       // rel_num
#define NBAGS    16384
#define NSENT    131072
#define BLOCK    256
#define WARPS    (BLOCK / 32)
#define MAX_LEN  512      // safe upper bound on bag length (mean ~8, max ~25)

// Flag: 1 if scope/X_Rel buffers hold int64, 0 if int32.
__device__ int g_idx64;

__global__ void detect_idx_dtype(const int* __restrict__ scope_as_i32) {
    // int64 little-endian: word 1 = high word of start0 (=0)  -> 0
    // int32:               word 1 = end0 (>=1)                -> nonzero
    g_idx64 = (scope_as_i32[1] == 0) ? 1 : 0;
}

__global__ __launch_bounds__(BLOCK)
void tan_fused_kernel(const float* __restrict__ X,
                      const void*  __restrict__ scope_raw,     // [B,2] i32 or i64
                      const float* __restrict__ Constraints,   // [REL,D]
                      const void*  __restrict__ xrel_raw,      // [B]   i32 or i64
                      const float* __restrict__ W_cls,         // [REL,D]
                      const float* __restrict__ b_cls,         // [REL]
                      float* __restrict__ out)                 // [B,REL]
{
    const int b    = blockIdx.x;
    const int tid  = threadIdx.x;
    const int lane = tid & 31;
    const int warp = tid >> 5;

    __shared__ float sCon[D];
    __shared__ float sBag[D];
    __shared__ float sScores[MAX_LEN];

    long long start, end, rel;
    if (g_idx64) {
        const long long* sc = (const long long*)scope_raw;
        start = sc[2 * b];
        end   = sc[2 * b + 1];
        rel   = ((const long long*)xrel_raw)[b];
    } else {
        const int* sc = (const int*)scope_raw;
        start = sc[2 * b];
        end   = sc[2 * b + 1];
        rel   = ((const int*)xrel_raw)[b];
    }
    // Defensive clamps: a wrong dtype guess yields rel_err, never an IMA.
    if (start < 0) start = 0;
    if (start > NSENT) start = NSENT;
    if (end < start) end = start;
    if (end > NSENT) end = NSENT;
    if (rel < 0) rel = 0;
    if (rel >= REL) rel = REL - 1;
    int len = (int)(end - start);
    if (len > MAX_LEN) len = MAX_LEN;

    // ---- Phase 1: stage query vector Con = Constraints[rel] into smem ----
    {
        const float4* __restrict__ Con4 = (const float4*)(Constraints + rel * D);
        float4* sCon4 = (float4*)sCon;
        for (int i = tid; i < D / 4; i += BLOCK) sCon4[i] = Con4[i];
    }
    __syncthreads();

    // ---- Phase 2: scores[s] = dot(X[start+s], Con), one warp per sentence ----
    // This is the single HBM pass over X (268 MB) — the kernel's roofline term.
    {
        const float4* sCon4 = (const float4*)sCon;
        for (int s = warp; s < len; s += WARPS) {
            const float4* __restrict__ row = (const float4*)(X + (start + s) * (long long)D);
            float acc = 0.f;
            #pragma unroll
            for (int i = 0; i < 4; i++) {          // 4 float4 per lane = 16 floats
                float4 x = row[lane + 32 * i];
                float4 c = sCon4[lane + 32 * i];
                acc += x.x * c.x + x.y * c.y + x.z * c.z + x.w * c.w;
            }
            #pragma unroll
            for (int off = 16; off; off >>= 1)
                acc += __shfl_xor_sync(0xffffffffu, acc, off);
            if (lane == 0) sScores[s] = acc;
        }
    }
    __syncthreads();

    // ---- Phase 3: softmax over the bag (warp 0; len is small) ----
    if (warp == 0) {
        float m = -INFINITY;
        for (int s = lane; s < len; s += 32) m = fmaxf(m, sScores[s]);
        #pragma unroll
        for (int off = 16; off; off >>= 1)
            m = fmaxf(m, __shfl_xor_sync(0xffffffffu, m, off));
        float sum = 0.f;
        for (int s = lane; s < len; s += 32) {
            float e = expf(sScores[s] - m);
            sScores[s] = e;
            sum += e;
        }
        #pragma unroll
        for (int off = 16; off; off >>= 1)
            sum += __shfl_xor_sync(0xffffffffu, sum, off);
        float inv = 1.f / sum;
        for (int s = lane; s < len; s += 32) sScores[s] *= inv;
    }
    __syncthreads();

    // ---- Phase 4: bag = sum_s w[s] * X[start+s]  (rows are L2-hot now) ----
    {
        float2 acc = make_float2(0.f, 0.f);
        for (int s = 0; s < len; s++) {
            const float w = sScores[s];
            const float2 x = ((const float2*)(X + (start + s) * (long long)D))[tid];
            acc.x = fmaf(w, x.x, acc.x);
            acc.y = fmaf(w, x.y, acc.y);
        }
        ((float2*)sBag)[tid] = acc;
    }
    __syncthreads();

    // ---- Phase 5: out[b] = bag @ W_cls^T + b_cls (W_cls is L2-resident) ----
    {
        const float4* sBag4 = (const float4*)sBag;
        for (int r = warp; r < REL; r += WARPS) {
            const float4* __restrict__ w4 = (const float4*)(W_cls + r * D);
            float acc = 0.f;
            #pragma unroll
            for (int i = 0; i < 4; i++) {
                float4 a = w4[lane + 32 * i];
                float4 g = sBag4[lane + 32 * i];
                acc += a.x * g.x + a.y * g.y + a.z * g.z + a.w * g.w;
            }
            #pragma unroll
            for (int off = 16; off; off >>= 1)
                acc += __shfl_xor_sync(0xffffffffu, acc, off);
            if (lane == 0) out[b * REL + r] = acc + b_cls[r];
        }
    }
}

extern "C" void kernel_launch(void* const* d_in, const int* in_sizes, int n_in,
                              void* d_out, int out_size) {
    // metadata order: X, X_Scope, Constraints, X_Rel, W_cls, b_cls
    const float* X     = (const float*)d_in[0];
    const void*  scope = d_in[1];
    const float* Con   = (const float*)d_in[2];
    const void*  xrel  = d_in[3];
    const float* Wc    = (const float*)d_in[4];
    const float* bc    = (const float*)d_in[5];
    float*       out   = (float*)d_out;

    detect_idx_dtype<<<1, 1>>>((const int*)scope);
    tan_fused_kernel<<<NBAGS, BLOCK>>>(X, scope, Con, xrel, Wc, bc, out);
}